// round 13
// baseline (speedup 1.0000x reference)
#include <cuda_runtime.h>
#include <cuda_fp16.h>
#include <cstdint>

// out[8192,4096] = x@W^T + ((x*mask)@A)@B   (fp32, SCALE=1)
// fp16 single-pass main GEMM; LoRA T via fp16 tensor-core GEMM (fp32 accum).
#define M_ALL 8192
#define N_ALL 4096
#define K_ALL 4096
#define RNK   32
#define TSLICES 4
#define TP_SLICES 8

// ---------------- scratch (__device__ globals; no allocs allowed) ------------
__device__ __align__(256) __half g_xhi[(size_t)M_ALL * K_ALL];
__device__ __align__(256) __half g_whi[(size_t)N_ALL * K_ALL];
__device__ __align__(256) __half g_tcat[(size_t)M_ALL * 64];    // [Th|Tl]
__device__ __align__(256) __half g_btcat[(size_t)N_ALL * 64];   // [Bh|Bh]
__device__ __align__(256) float g_tpart[TP_SLICES][M_ALL][RNK];

// ---------------- PTX helpers -------------------------------------------------
__device__ __forceinline__ uint32_t smem_u32(const void* p) {
    uint32_t a;
    asm("{ .reg .u64 t; cvta.to.shared.u64 t, %1; cvt.u32.u64 %0, t; }" : "=r"(a) : "l"(p));
    return a;
}
#define CP_ASYNC16(dst, src) \
    asm volatile("cp.async.cg.shared.global [%0], [%1], 16;" :: "r"((uint32_t)(dst)), "l"(src))
#define CP_ASYNC_COMMIT() asm volatile("cp.async.commit_group;" ::: "memory")
#define CP_ASYNC_WAIT(n)  asm volatile("cp.async.wait_group %0;" :: "n"(n) : "memory")

__device__ __forceinline__ void ldmatrix_x4(uint32_t* r, uint32_t addr) {
    asm volatile("ldmatrix.sync.aligned.m8n8.x4.shared.b16 {%0,%1,%2,%3}, [%4];"
                 : "=r"(r[0]), "=r"(r[1]), "=r"(r[2]), "=r"(r[3]) : "r"(addr));
}
__device__ __forceinline__ void mma_fp16(float* d, const uint32_t* a, uint32_t b0, uint32_t b1) {
    asm volatile(
        "mma.sync.aligned.m16n8k16.row.col.f32.f16.f16.f32 "
        "{%0,%1,%2,%3}, {%4,%5,%6,%7}, {%8,%9}, {%0,%1,%2,%3};"
        : "+f"(d[0]), "+f"(d[1]), "+f"(d[2]), "+f"(d[3])
        : "r"(a[0]), "r"(a[1]), "r"(a[2]), "r"(a[3]), "r"(b0), "r"(b1));
}
__device__ __forceinline__ void split1h(float v, __half& h, __half& l) {
    h = __float2half(v);
    l = __float2half(v - __half2float(h));
}

// ---------------- kernel #1: T partials (tensor core) + x->fp16 + W->fp16 ------
#define T_BLOCKS 512
#define W_BLOCKS 4096
#define TP_PITCH 272
#define TP_XM_BYTES (64 * TP_PITCH)
#define TP_AT_BYTES (32 * TP_PITCH)
#define T_SMEM_BYTES (TP_XM_BYTES + TP_AT_BYTES)   // 26112

__global__ void __launch_bounds__(256) prep1_kernel(const float* __restrict__ x,
                                                    const float* __restrict__ mask,
                                                    const float* __restrict__ A,
                                                    const float4* __restrict__ W) {
    extern __shared__ __align__(16) char tsm[];
    const int tid = threadIdx.x;
    const int bid = blockIdx.x;

    if (bid >= T_BLOCKS) {
        size_t base = (size_t)(bid - T_BLOCKS) * 1024 + tid;
        __half2* hi = reinterpret_cast<__half2*>(g_whi);
        float4 v[4];
#pragma unroll
        for (int u = 0; u < 4; ++u) v[u] = W[base + u * 256];
#pragma unroll
        for (int u = 0; u < 4; ++u) {
            size_t i = base + u * 256;
            hi[2 * i]     = __halves2half2(__float2half(v[u].x), __float2half(v[u].y));
            hi[2 * i + 1] = __halves2half2(__float2half(v[u].z), __float2half(v[u].w));
        }
        return;
    }

    const uint32_t smem_base = smem_u32(tsm);
    const uint32_t xm_base = smem_base;
    const uint32_t at_base = smem_base + TP_XM_BYTES;
    const int wid = tid >> 5;
    const int lane = tid & 31;
    const int slice = bid >> 7;
    const int m0 = (bid & 127) * 64;
    const int kbase = slice * (K_ALL / TSLICES);
    const int mw = (wid & 3) * 16;
    const int kh = wid >> 2;

    const uint32_t a_addr = xm_base + (uint32_t)(mw + (lane & 15)) * TP_PITCH +
                            (uint32_t)((lane >> 4) * 16 + kh * 128);
    uint32_t b_addr[2];
#pragma unroll
    for (int jj = 0; jj < 2; ++jj)
        b_addr[jj] = at_base +
                     (uint32_t)(jj * 16 + ((lane >> 4) << 3) + (lane & 7)) * TP_PITCH +
                     (uint32_t)(((lane >> 3) & 1) * 16 + kh * 128);

    float acc[4][4];
#pragma unroll
    for (int j = 0; j < 4; ++j)
#pragma unroll
        for (int v = 0; v < 4; ++v) acc[j][v] = 0.f;

    const float4* x4 = reinterpret_cast<const float4*>(x);
    const float4* m4 = reinterpret_cast<const float4*>(mask);
    __half2* xh2 = reinterpret_cast<__half2*>(g_xhi);

    for (int kc = 0; kc < K_ALL / TSLICES; kc += 128) {
        __syncthreads();
#pragma unroll
        for (int i = 0; i < 8; ++i) {
            int idx = tid + i * 256;
            int row = idx >> 5, c4 = idx & 31;
            size_t g = ((size_t)(m0 + row) * K_ALL + kbase + kc) / 4 + c4;
            float4 xv = x4[g];
            float4 mv = m4[g];
            xh2[2 * g]     = __halves2half2(__float2half(xv.x), __float2half(xv.y));
            xh2[2 * g + 1] = __halves2half2(__float2half(xv.z), __float2half(xv.w));
            __half2* dst = reinterpret_cast<__half2*>(tsm + row * TP_PITCH + c4 * 8);
            dst[0] = __halves2half2(__float2half(xv.x * mv.x), __float2half(xv.y * mv.y));
            dst[1] = __halves2half2(__float2half(xv.z * mv.z), __float2half(xv.w * mv.w));
        }
#pragma unroll
        for (int i = 0; i < 16; ++i) {
            int idx = tid + i * 256;
            int kk = idx >> 5, r = idx & 31;
            *reinterpret_cast<__half*>(tsm + TP_XM_BYTES + r * TP_PITCH + kk * 2) =
                __float2half(A[(size_t)(kbase + kc + kk) * RNK + r]);
        }
        __syncthreads();
#pragma unroll
        for (int ks = 0; ks < 4; ++ks) {
            uint32_t a[4], b[2][4];
            ldmatrix_x4(a, a_addr + ks * 32);
            ldmatrix_x4(b[0], b_addr[0] + ks * 32);
            ldmatrix_x4(b[1], b_addr[1] + ks * 32);
#pragma unroll
            for (int j = 0; j < 4; ++j)
                mma_fp16(acc[j], a, b[j >> 1][(j & 1) * 2], b[j >> 1][(j & 1) * 2 + 1]);
        }
    }
    const int sl = slice * 2 + kh;
    const int g8 = lane >> 2;
    const int t4 = lane & 3;
#pragma unroll
    for (int j = 0; j < 4; ++j) {
        int r = j * 8 + t4 * 2;
        int m = m0 + mw + g8;
        *reinterpret_cast<float2*>(&g_tpart[sl][m][r]) = make_float2(acc[j][0], acc[j][1]);
        *reinterpret_cast<float2*>(&g_tpart[sl][m + 8][r]) = make_float2(acc[j][2], acc[j][3]);
    }
}

// ---------------- kernel #2: B pack (16 blocks) + t_pack (256 blocks) ----------
__global__ void __launch_bounds__(256) prep2_kernel(const float* __restrict__ Bm) {
    const int b = blockIdx.x;
    const int tid = threadIdx.x;
    if (b < 16) {
        int n = b * 256 + tid;
        __half* row = g_btcat + (size_t)n * 64;
#pragma unroll
        for (int r = 0; r < RNK; ++r) {
            __half h = __float2half(Bm[(size_t)r * N_ALL + n]);
            row[r] = h; row[32 + r] = h;
        }
    } else {
        int idx = (b - 16) * 256 + tid;
        int m = idx >> 3, rg = idx & 7, r = rg * 4;
        __half* row = g_tcat + (size_t)m * 64;
#pragma unroll
        for (int j = 0; j < 4; ++j) {
            float s = 0.f;
#pragma unroll
            for (int sl = 0; sl < TP_SLICES; ++sl) s += g_tpart[sl][m][r + j];
            __half h, l;
            split1h(s, h, l);
            row[r + j] = h; row[32 + r + j] = l;
        }
    }
}

// ---------------- fused GEMM ---------------------------------------------------
// CTA tile 128x128, 128 threads (4 warps = 2M x 2N, warp tile 64x64), 2 CTAs/SM.
// Halves smem-read traffic per MAC vs 64x32 warp tiles (fragment reuse 2x).
// 65 K-chunks of 64:  [0,64): xh@Wh   [64]: [Th|Tl]@[Bh|Bh]
#define NCHUNK 65
#define PITCH_B 144
#define A_BYTES (128 * PITCH_B)
#define B_BYTES (128 * PITCH_B)
#define STAGE_BYTES (A_BYTES + B_BYTES)  // 36864
#define NSTAGE 3
#define GEMM_SMEM (NSTAGE * STAGE_BYTES) // 110592

__device__ __forceinline__ void load_chunk(int c, int stage, int tid, int m0, int n0,
                                           uint32_t smem_base) {
    const __half *pa, *pb;
    int lda, ldb, k0;
    if (c < 64) { pa = g_xhi;  pb = g_whi;   lda = K_ALL; ldb = K_ALL; k0 = c << 6; }
    else        { pa = g_tcat; pb = g_btcat; lda = 64;    ldb = 64;    k0 = 0; }
    uint32_t sA = smem_base + stage * STAGE_BYTES;
    uint32_t sB = sA + A_BYTES;
#pragma unroll
    for (int i = 0; i < 8; ++i) {
        int op = tid + i * 128;
        int row = op >> 3, col = op & 7;
        CP_ASYNC16(sA + (uint32_t)(row * PITCH_B + col * 16),
                   pa + (size_t)(m0 + row) * lda + k0 + col * 8);
        CP_ASYNC16(sB + (uint32_t)(row * PITCH_B + col * 16),
                   pb + (size_t)(n0 + row) * ldb + k0 + col * 8);
    }
}

// kernel #3: the GEMM
__global__ void __launch_bounds__(128, 2)
lora_gemm_kernel(float* __restrict__ out) {
    extern __shared__ __align__(1024) char smem[];
    const uint32_t smem_base = smem_u32(smem);
    const int tid = threadIdx.x;
    const int wid = tid >> 5;
    const int lane = tid & 31;
    // raster: groups of 16 m-tiles x 32 n-tiles
    const int gid = blockIdx.x >> 9;
    const int rr  = blockIdx.x & 511;
    const int m0 = (gid * 16 + (rr & 15)) * 128;
    const int n0 = (rr >> 4) * 128;
    const int m_w = (wid >> 1) * 64;     // 2 m-warps
    const int n_w = (wid & 1) * 64;      // 2 n-warps

    uint32_t aoff[4];
#pragma unroll
    for (int f = 0; f < 4; ++f)
        aoff[f] = (uint32_t)((m_w + f * 16 + (lane & 15)) * PITCH_B + (lane >> 4) * 16);
    uint32_t boff[4];
#pragma unroll
    for (int jj = 0; jj < 4; ++jj)
        boff[jj] = (uint32_t)(A_BYTES +
                              (n_w + jj * 16 + ((lane >> 4) << 3) + (lane & 7)) * PITCH_B +
                              ((lane >> 3) & 1) * 16);

    float acc[4][8][4];
#pragma unroll
    for (int f = 0; f < 4; ++f)
#pragma unroll
        for (int j = 0; j < 8; ++j)
#pragma unroll
            for (int v = 0; v < 4; ++v) acc[f][j][v] = 0.f;

    load_chunk(0, 0, tid, m0, n0, smem_base);
    CP_ASYNC_COMMIT();
    load_chunk(1, 1, tid, m0, n0, smem_base);
    CP_ASYNC_COMMIT();

    int st_c = 0, st_l = 2;
    for (int c = 0; c < NCHUNK; ++c) {
        CP_ASYNC_WAIT(1);
        __syncthreads();
        const int cl = c + 2;
        const uint32_t sbase = smem_base + st_c * STAGE_BYTES;

        // per-ks interleave; next chunk's cp.async in the ks==1 shadow
#pragma unroll
        for (int ks = 0; ks < 4; ++ks) {
            uint32_t a[4][4], b[4][4];
#pragma unroll
            for (int jj = 0; jj < 4; ++jj) ldmatrix_x4(b[jj], sbase + boff[jj] + ks * 32);
#pragma unroll
            for (int f = 0; f < 4; ++f) ldmatrix_x4(a[f], sbase + aoff[f] + ks * 32);
            if (ks == 1 && cl < NCHUNK) load_chunk(cl, st_l, tid, m0, n0, smem_base);
#pragma unroll
            for (int f = 0; f < 4; ++f)
#pragma unroll
                for (int j = 0; j < 8; ++j)
                    mma_fp16(acc[f][j], a[f], b[j >> 1][(j & 1) * 2], b[j >> 1][(j & 1) * 2 + 1]);
        }
        CP_ASYNC_COMMIT();
        st_c = (st_c + 1 == NSTAGE) ? 0 : st_c + 1;
        st_l = (st_l + 1 == NSTAGE) ? 0 : st_l + 1;
    }

    // epilogue
    const int g8 = lane >> 2;
    const int t4 = lane & 3;
#pragma unroll
    for (int f = 0; f < 4; ++f) {
        const int mrow = m0 + m_w + f * 16 + g8;
#pragma unroll
        for (int j = 0; j < 8; ++j) {
            const int ncol = n0 + n_w + j * 8 + t4 * 2;
            float2 v0 = make_float2(acc[f][j][0], acc[f][j][1]);
            float2 v1 = make_float2(acc[f][j][2], acc[f][j][3]);
            *reinterpret_cast<float2*>(out + (size_t)mrow * N_ALL + ncol) = v0;
            *reinterpret_cast<float2*>(out + (size_t)(mrow + 8) * N_ALL + ncol) = v1;
        }
    }
}

// ---------------- launch ---------------------------------------------------------
extern "C" void kernel_launch(void* const* d_in, const int* in_sizes, int n_in,
                              void* d_out, int out_size) {
    const float* x    = (const float*)d_in[0];   // [8192, 4096]
    const float* W    = (const float*)d_in[1];   // [4096, 4096]
    const float* A    = (const float*)d_in[2];   // [4096, 32]
    const float* Bm   = (const float*)d_in[3];   // [32, 4096]
    const float* mask = (const float*)d_in[4];   // [8192, 4096]
    float* out = (float*)d_out;

    static bool attr_set = false;
    if (!attr_set) {
        cudaFuncSetAttribute(lora_gemm_kernel,
                             cudaFuncAttributeMaxDynamicSharedMemorySize, GEMM_SMEM);
        cudaFuncSetAttribute(prep1_kernel,
                             cudaFuncAttributeMaxDynamicSharedMemorySize, T_SMEM_BYTES);
        attr_set = true;
    }

    prep1_kernel<<<T_BLOCKS + W_BLOCKS, 256, T_SMEM_BYTES>>>(x, mask, A, (const float4*)W);
    prep2_kernel<<<272, 256>>>(Bm);
    lora_gemm_kernel<<<2048, 128, GEMM_SMEM>>>(out);
}

// round 14
// speedup vs baseline: 1.0307x; 1.0307x over previous
#include <cuda_runtime.h>
#include <cuda_fp16.h>
#include <cstdint>

// out[8192,4096] = x@W^T + ((x*mask)@A)@B   (fp32, SCALE=1)
// fp16 single-pass main GEMM; LoRA T via fp16 tensor-core GEMM (fp32 accum).
#define M_ALL 8192
#define N_ALL 4096
#define K_ALL 4096
#define RNK   32
#define TSLICES 8          // K-slices (512 wide each)
#define TP_SLICES 16       // TSLICES * 2 k-halves

// ---------------- scratch (__device__ globals; no allocs allowed) ------------
__device__ __align__(256) __half g_xhi[(size_t)M_ALL * K_ALL];
__device__ __align__(256) __half g_whi[(size_t)N_ALL * K_ALL];
__device__ __align__(256) __half g_tcat[(size_t)M_ALL * 64];    // [Th|Tl]
__device__ __align__(256) __half g_btcat[(size_t)N_ALL * 64];   // [Bh|Bh]
__device__ __align__(256) float g_tpart[TP_SLICES][M_ALL][RNK];

// ---------------- PTX helpers -------------------------------------------------
__device__ __forceinline__ uint32_t smem_u32(const void* p) {
    uint32_t a;
    asm("{ .reg .u64 t; cvta.to.shared.u64 t, %1; cvt.u32.u64 %0, t; }" : "=r"(a) : "l"(p));
    return a;
}
#define CP_ASYNC16(dst, src) \
    asm volatile("cp.async.cg.shared.global [%0], [%1], 16;" :: "r"((uint32_t)(dst)), "l"(src))
#define CP_ASYNC_COMMIT() asm volatile("cp.async.commit_group;" ::: "memory")
#define CP_ASYNC_WAIT(n)  asm volatile("cp.async.wait_group %0;" :: "n"(n) : "memory")

__device__ __forceinline__ void ldmatrix_x4(uint32_t* r, uint32_t addr) {
    asm volatile("ldmatrix.sync.aligned.m8n8.x4.shared.b16 {%0,%1,%2,%3}, [%4];"
                 : "=r"(r[0]), "=r"(r[1]), "=r"(r[2]), "=r"(r[3]) : "r"(addr));
}
__device__ __forceinline__ void mma_fp16(float* d, const uint32_t* a, uint32_t b0, uint32_t b1) {
    asm volatile(
        "mma.sync.aligned.m16n8k16.row.col.f32.f16.f16.f32 "
        "{%0,%1,%2,%3}, {%4,%5,%6,%7}, {%8,%9}, {%0,%1,%2,%3};"
        : "+f"(d[0]), "+f"(d[1]), "+f"(d[2]), "+f"(d[3])
        : "r"(a[0]), "r"(a[1]), "r"(a[2]), "r"(a[3]), "r"(b0), "r"(b1));
}
__device__ __forceinline__ void split1h(float v, __half& h, __half& l) {
    h = __float2half(v);
    l = __float2half(v - __half2float(h));
}

// ---------------- kernel #1: T partials (tensor core) + x->fp16 + W->fp16 ------
// bid < 1024: t-block (64 m-rows, K-slice 512, fused x conversion, fp16 mma)
// bid >= 1024: W conversion block (4 float4 per thread)
#define T_BLOCKS 1024
#define W_BLOCKS 4096
#define TP_PITCH 272
#define TP_XM_BYTES (64 * TP_PITCH)
#define TP_AT_BYTES (32 * TP_PITCH)
#define T_SMEM_BYTES (TP_XM_BYTES + TP_AT_BYTES)   // 26112

__global__ void __launch_bounds__(256) prep1_kernel(const float* __restrict__ x,
                                                    const float* __restrict__ mask,
                                                    const float* __restrict__ A,
                                                    const float4* __restrict__ W) {
    extern __shared__ __align__(16) char tsm[];
    const int tid = threadIdx.x;
    const int bid = blockIdx.x;

    if (bid >= T_BLOCKS) {
        size_t base = (size_t)(bid - T_BLOCKS) * 1024 + tid;
        __half2* hi = reinterpret_cast<__half2*>(g_whi);
        float4 v[4];
#pragma unroll
        for (int u = 0; u < 4; ++u) v[u] = W[base + u * 256];
#pragma unroll
        for (int u = 0; u < 4; ++u) {
            size_t i = base + u * 256;
            hi[2 * i]     = __halves2half2(__float2half(v[u].x), __float2half(v[u].y));
            hi[2 * i + 1] = __halves2half2(__float2half(v[u].z), __float2half(v[u].w));
        }
        return;
    }

    const uint32_t smem_base = smem_u32(tsm);
    const uint32_t xm_base = smem_base;
    const uint32_t at_base = smem_base + TP_XM_BYTES;
    const int wid = tid >> 5;
    const int lane = tid & 31;
    const int slice = bid >> 7;            // 0..7
    const int m0 = (bid & 127) * 64;
    const int kbase = slice * (K_ALL / TSLICES);
    const int mw = (wid & 3) * 16;
    const int kh = wid >> 2;

    const uint32_t a_addr = xm_base + (uint32_t)(mw + (lane & 15)) * TP_PITCH +
                            (uint32_t)((lane >> 4) * 16 + kh * 128);
    uint32_t b_addr[2];
#pragma unroll
    for (int jj = 0; jj < 2; ++jj)
        b_addr[jj] = at_base +
                     (uint32_t)(jj * 16 + ((lane >> 4) << 3) + (lane & 7)) * TP_PITCH +
                     (uint32_t)(((lane >> 3) & 1) * 16 + kh * 128);

    float acc[4][4];
#pragma unroll
    for (int j = 0; j < 4; ++j)
#pragma unroll
        for (int v = 0; v < 4; ++v) acc[j][v] = 0.f;

    const float4* x4 = reinterpret_cast<const float4*>(x);
    const float4* m4 = reinterpret_cast<const float4*>(mask);
    __half2* xh2 = reinterpret_cast<__half2*>(g_xhi);

    for (int kc = 0; kc < K_ALL / TSLICES; kc += 128) {
        __syncthreads();
#pragma unroll
        for (int i = 0; i < 8; ++i) {
            int idx = tid + i * 256;
            int row = idx >> 5, c4 = idx & 31;
            size_t g = ((size_t)(m0 + row) * K_ALL + kbase + kc) / 4 + c4;
            float4 xv = x4[g];
            float4 mv = m4[g];
            xh2[2 * g]     = __halves2half2(__float2half(xv.x), __float2half(xv.y));
            xh2[2 * g + 1] = __halves2half2(__float2half(xv.z), __float2half(xv.w));
            __half2* dst = reinterpret_cast<__half2*>(tsm + row * TP_PITCH + c4 * 8);
            dst[0] = __halves2half2(__float2half(xv.x * mv.x), __float2half(xv.y * mv.y));
            dst[1] = __halves2half2(__float2half(xv.z * mv.z), __float2half(xv.w * mv.w));
        }
#pragma unroll
        for (int i = 0; i < 16; ++i) {
            int idx = tid + i * 256;
            int kk = idx >> 5, r = idx & 31;
            *reinterpret_cast<__half*>(tsm + TP_XM_BYTES + r * TP_PITCH + kk * 2) =
                __float2half(A[(size_t)(kbase + kc + kk) * RNK + r]);
        }
        __syncthreads();
#pragma unroll
        for (int ks = 0; ks < 4; ++ks) {
            uint32_t a[4], b[2][4];
            ldmatrix_x4(a, a_addr + ks * 32);
            ldmatrix_x4(b[0], b_addr[0] + ks * 32);
            ldmatrix_x4(b[1], b_addr[1] + ks * 32);
#pragma unroll
            for (int j = 0; j < 4; ++j)
                mma_fp16(acc[j], a, b[j >> 1][(j & 1) * 2], b[j >> 1][(j & 1) * 2 + 1]);
        }
    }
    const int sl = slice * 2 + kh;
    const int g8 = lane >> 2;
    const int t4 = lane & 3;
#pragma unroll
    for (int j = 0; j < 4; ++j) {
        int r = j * 8 + t4 * 2;
        int m = m0 + mw + g8;
        *reinterpret_cast<float2*>(&g_tpart[sl][m][r]) = make_float2(acc[j][0], acc[j][1]);
        *reinterpret_cast<float2*>(&g_tpart[sl][m + 8][r]) = make_float2(acc[j][2], acc[j][3]);
    }
}

// ---------------- kernel #2: B pack (16 blocks) + t_pack (256 blocks) ----------
__global__ void __launch_bounds__(256) prep2_kernel(const float* __restrict__ Bm) {
    const int b = blockIdx.x;
    const int tid = threadIdx.x;
    if (b < 16) {
        int n = b * 256 + tid;
        __half* row = g_btcat + (size_t)n * 64;
#pragma unroll
        for (int r = 0; r < RNK; ++r) {
            __half h = __float2half(Bm[(size_t)r * N_ALL + n]);
            row[r] = h; row[32 + r] = h;
        }
    } else {
        int idx = (b - 16) * 256 + tid;
        int m = idx >> 3, rg = idx & 7, r = rg * 4;
        __half* row = g_tcat + (size_t)m * 64;
#pragma unroll
        for (int j = 0; j < 4; ++j) {
            float s = 0.f;
#pragma unroll
            for (int sl = 0; sl < TP_SLICES; ++sl) s += g_tpart[sl][m][r + j];
            __half h, l;
            split1h(s, h, l);
            row[r + j] = h; row[32 + r + j] = l;
        }
    }
}

// ---------------- fused GEMM (R11 configuration — empirical optimum) -----------
// CTA tile 128x128, 256 threads (8 warps = 2M x 4N, warp tile 64x32), 2 CTAs/SM.
// 65 K-chunks of 64:  [0,64): xh@Wh   [64]: [Th|Tl]@[Bh|Bh]
#define NCHUNK 65
#define PITCH_B 144
#define A_BYTES (128 * PITCH_B)
#define B_BYTES (128 * PITCH_B)
#define STAGE_BYTES (A_BYTES + B_BYTES)  // 36864
#define NSTAGE 3
#define GEMM_SMEM (NSTAGE * STAGE_BYTES) // 110592

__device__ __forceinline__ void load_chunk(int c, int stage, int tid, int m0, int n0,
                                           uint32_t smem_base) {
    const __half *pa, *pb;
    int lda, ldb, k0;
    if (c < 64) { pa = g_xhi;  pb = g_whi;   lda = K_ALL; ldb = K_ALL; k0 = c << 6; }
    else        { pa = g_tcat; pb = g_btcat; lda = 64;    ldb = 64;    k0 = 0; }
    uint32_t sA = smem_base + stage * STAGE_BYTES;
    uint32_t sB = sA + A_BYTES;
#pragma unroll
    for (int i = 0; i < 4; ++i) {
        int op = tid + i * 256;
        int row = op >> 3, col = op & 7;
        CP_ASYNC16(sA + (uint32_t)(row * PITCH_B + col * 16),
                   pa + (size_t)(m0 + row) * lda + k0 + col * 8);
        CP_ASYNC16(sB + (uint32_t)(row * PITCH_B + col * 16),
                   pb + (size_t)(n0 + row) * ldb + k0 + col * 8);
    }
}

// kernel #3: the GEMM
__global__ void __launch_bounds__(256, 2)
lora_gemm_kernel(float* __restrict__ out) {
    extern __shared__ __align__(1024) char smem[];
    const uint32_t smem_base = smem_u32(smem);
    const int tid = threadIdx.x;
    const int wid = tid >> 5;
    const int lane = tid & 31;
    // raster: groups of 16 m-tiles x 32 n-tiles
    const int gid = blockIdx.x >> 9;
    const int rr  = blockIdx.x & 511;
    const int m0 = (gid * 16 + (rr & 15)) * 128;
    const int n0 = (rr >> 4) * 128;
    const int m_w = (wid >> 2) * 64;
    const int n_w = (wid & 3) * 32;

    uint32_t aoff[4];
#pragma unroll
    for (int f = 0; f < 4; ++f)
        aoff[f] = (uint32_t)((m_w + f * 16 + (lane & 15)) * PITCH_B + (lane >> 4) * 16);
    uint32_t boff[2];
#pragma unroll
    for (int jj = 0; jj < 2; ++jj)
        boff[jj] = (uint32_t)(A_BYTES +
                              (n_w + jj * 16 + ((lane >> 4) << 3) + (lane & 7)) * PITCH_B +
                              ((lane >> 3) & 1) * 16);

    float acc[4][4][4];
#pragma unroll
    for (int f = 0; f < 4; ++f)
#pragma unroll
        for (int j = 0; j < 4; ++j)
#pragma unroll
            for (int v = 0; v < 4; ++v) acc[f][j][v] = 0.f;

    load_chunk(0, 0, tid, m0, n0, smem_base);
    CP_ASYNC_COMMIT();
    load_chunk(1, 1, tid, m0, n0, smem_base);
    CP_ASYNC_COMMIT();

    int st_c = 0, st_l = 2;
    for (int c = 0; c < NCHUNK; ++c) {
        CP_ASYNC_WAIT(1);
        __syncthreads();
        const int cl = c + 2;
        const uint32_t sbase = smem_base + st_c * STAGE_BYTES;

        // per-ks interleave; next chunk's cp.async in the ks==1 shadow
#pragma unroll
        for (int ks = 0; ks < 4; ++ks) {
            uint32_t a[4][4], b[2][4];
#pragma unroll
            for (int jj = 0; jj < 2; ++jj) ldmatrix_x4(b[jj], sbase + boff[jj] + ks * 32);
#pragma unroll
            for (int f = 0; f < 4; ++f) ldmatrix_x4(a[f], sbase + aoff[f] + ks * 32);
            if (ks == 1 && cl < NCHUNK) load_chunk(cl, st_l, tid, m0, n0, smem_base);
#pragma unroll
            for (int f = 0; f < 4; ++f)
#pragma unroll
                for (int j = 0; j < 4; ++j)
                    mma_fp16(acc[f][j], a[f], b[j >> 1][(j & 1) * 2], b[j >> 1][(j & 1) * 2 + 1]);
        }
        CP_ASYNC_COMMIT();
        st_c = (st_c + 1 == NSTAGE) ? 0 : st_c + 1;
        st_l = (st_l + 1 == NSTAGE) ? 0 : st_l + 1;
    }

    // epilogue
    const int g8 = lane >> 2;
    const int t4 = lane & 3;
#pragma unroll
    for (int f = 0; f < 4; ++f) {
        const int mrow = m0 + m_w + f * 16 + g8;
#pragma unroll
        for (int j = 0; j < 4; ++j) {
            const int ncol = n0 + n_w + j * 8 + t4 * 2;
            float2 v0 = make_float2(acc[f][j][0], acc[f][j][1]);
            float2 v1 = make_float2(acc[f][j][2], acc[f][j][3]);
            *reinterpret_cast<float2*>(out + (size_t)mrow * N_ALL + ncol) = v0;
            *reinterpret_cast<float2*>(out + (size_t)(mrow + 8) * N_ALL + ncol) = v1;
        }
    }
}

// ---------------- launch ---------------------------------------------------------
extern "C" void kernel_launch(void* const* d_in, const int* in_sizes, int n_in,
                              void* d_out, int out_size) {
    const float* x    = (const float*)d_in[0];   // [8192, 4096]
    const float* W    = (const float*)d_in[1];   // [4096, 4096]
    const float* A    = (const float*)d_in[2];   // [4096, 32]
    const float* Bm   = (const float*)d_in[3];   // [32, 4096]
    const float* mask = (const float*)d_in[4];   // [8192, 4096]
    float* out = (float*)d_out;

    static bool attr_set = false;
    if (!attr_set) {
        cudaFuncSetAttribute(lora_gemm_kernel,
                             cudaFuncAttributeMaxDynamicSharedMemorySize, GEMM_SMEM);
        cudaFuncSetAttribute(prep1_kernel,
                             cudaFuncAttributeMaxDynamicSharedMemorySize, T_SMEM_BYTES);
        attr_set = true;
    }

    prep1_kernel<<<T_BLOCKS + W_BLOCKS, 256, T_SMEM_BYTES>>>(x, mask, A, (const float4*)W);
    prep2_kernel<<<272, 256>>>(Bm);
    lora_gemm_kernel<<<2048, 256, GEMM_SMEM>>>(out);
}

// round 15
// speedup vs baseline: 1.0865x; 1.0541x over previous
#include <cuda_runtime.h>
#include <cuda_fp16.h>
#include <cstdint>

// out[8192,4096] = x@W^T + ((x*mask)@A)@B   (fp32, SCALE=1)
// fp16 single-pass main GEMM; LoRA T via fp16 tensor-core GEMM (fp32 accum).
#define M_ALL 8192
#define N_ALL 4096
#define K_ALL 4096
#define RNK   32
#define TSLICES 8
#define TP_SLICES 16

// ---------------- scratch (__device__ globals; no allocs allowed) ------------
__device__ __align__(256) __half g_xhi[(size_t)M_ALL * K_ALL];
__device__ __align__(256) __half g_whi[(size_t)N_ALL * K_ALL];
__device__ __align__(256) __half g_tcat[(size_t)M_ALL * 64];    // [Th|Tl]
__device__ __align__(256) __half g_btcat[(size_t)N_ALL * 64];   // [Bh|Bh]
__device__ __align__(256) float g_tpart[TP_SLICES][M_ALL][RNK];

// ---------------- PTX helpers -------------------------------------------------
__device__ __forceinline__ uint32_t smem_u32(const void* p) {
    uint32_t a;
    asm("{ .reg .u64 t; cvta.to.shared.u64 t, %1; cvt.u32.u64 %0, t; }" : "=r"(a) : "l"(p));
    return a;
}
#define CP_ASYNC16(dst, src) \
    asm volatile("cp.async.cg.shared.global [%0], [%1], 16;" :: "r"((uint32_t)(dst)), "l"(src))
#define CP_ASYNC_COMMIT() asm volatile("cp.async.commit_group;" ::: "memory")
#define CP_ASYNC_WAIT(n)  asm volatile("cp.async.wait_group %0;" :: "n"(n) : "memory")

__device__ __forceinline__ void ldmatrix_x4(uint32_t* r, uint32_t addr) {
    asm volatile("ldmatrix.sync.aligned.m8n8.x4.shared.b16 {%0,%1,%2,%3}, [%4];"
                 : "=r"(r[0]), "=r"(r[1]), "=r"(r[2]), "=r"(r[3]) : "r"(addr));
}
__device__ __forceinline__ void mma_fp16(float* d, const uint32_t* a, uint32_t b0, uint32_t b1) {
    asm volatile(
        "mma.sync.aligned.m16n8k16.row.col.f32.f16.f16.f32 "
        "{%0,%1,%2,%3}, {%4,%5,%6,%7}, {%8,%9}, {%0,%1,%2,%3};"
        : "+f"(d[0]), "+f"(d[1]), "+f"(d[2]), "+f"(d[3])
        : "r"(a[0]), "r"(a[1]), "r"(a[2]), "r"(a[3]), "r"(b0), "r"(b1));
}
__device__ __forceinline__ void split1h(float v, __half& h, __half& l) {
    h = __float2half(v);
    l = __float2half(v - __half2float(h));
}

// ---------------- kernel #1: T partials (tensor core) + x->fp16 + W->fp16 ------
#define T_BLOCKS 1024
#define W_BLOCKS 4096
#define TP_PITCH 272
#define TP_XM_BYTES (64 * TP_PITCH)
#define TP_AT_BYTES (32 * TP_PITCH)
#define T_SMEM_BYTES (TP_XM_BYTES + TP_AT_BYTES)   // 26112

__global__ void __launch_bounds__(256) prep1_kernel(const float* __restrict__ x,
                                                    const float* __restrict__ mask,
                                                    const float* __restrict__ A,
                                                    const float4* __restrict__ W) {
    extern __shared__ __align__(16) char tsm[];
    const int tid = threadIdx.x;
    const int bid = blockIdx.x;

    if (bid >= T_BLOCKS) {
        size_t base = (size_t)(bid - T_BLOCKS) * 1024 + tid;
        __half2* hi = reinterpret_cast<__half2*>(g_whi);
        float4 v[4];
#pragma unroll
        for (int u = 0; u < 4; ++u) v[u] = W[base + u * 256];
#pragma unroll
        for (int u = 0; u < 4; ++u) {
            size_t i = base + u * 256;
            hi[2 * i]     = __halves2half2(__float2half(v[u].x), __float2half(v[u].y));
            hi[2 * i + 1] = __halves2half2(__float2half(v[u].z), __float2half(v[u].w));
        }
        return;
    }

    const uint32_t smem_base = smem_u32(tsm);
    const uint32_t xm_base = smem_base;
    const uint32_t at_base = smem_base + TP_XM_BYTES;
    const int wid = tid >> 5;
    const int lane = tid & 31;
    const int slice = bid >> 7;            // 0..7
    const int m0 = (bid & 127) * 64;
    const int kbase = slice * (K_ALL / TSLICES);
    const int mw = (wid & 3) * 16;
    const int kh = wid >> 2;

    const uint32_t a_addr = xm_base + (uint32_t)(mw + (lane & 15)) * TP_PITCH +
                            (uint32_t)((lane >> 4) * 16 + kh * 128);
    uint32_t b_addr[2];
#pragma unroll
    for (int jj = 0; jj < 2; ++jj)
        b_addr[jj] = at_base +
                     (uint32_t)(jj * 16 + ((lane >> 4) << 3) + (lane & 7)) * TP_PITCH +
                     (uint32_t)(((lane >> 3) & 1) * 16 + kh * 128);

    float acc[4][4];
#pragma unroll
    for (int j = 0; j < 4; ++j)
#pragma unroll
        for (int v = 0; v < 4; ++v) acc[j][v] = 0.f;

    const float4* x4 = reinterpret_cast<const float4*>(x);
    const float4* m4 = reinterpret_cast<const float4*>(mask);
    __half2* xh2 = reinterpret_cast<__half2*>(g_xhi);

    for (int kc = 0; kc < K_ALL / TSLICES; kc += 128) {
        __syncthreads();
#pragma unroll
        for (int i = 0; i < 8; ++i) {
            int idx = tid + i * 256;
            int row = idx >> 5, c4 = idx & 31;
            size_t g = ((size_t)(m0 + row) * K_ALL + kbase + kc) / 4 + c4;
            float4 xv = x4[g];
            float4 mv = m4[g];
            xh2[2 * g]     = __halves2half2(__float2half(xv.x), __float2half(xv.y));
            xh2[2 * g + 1] = __halves2half2(__float2half(xv.z), __float2half(xv.w));
            __half2* dst = reinterpret_cast<__half2*>(tsm + row * TP_PITCH + c4 * 8);
            dst[0] = __halves2half2(__float2half(xv.x * mv.x), __float2half(xv.y * mv.y));
            dst[1] = __halves2half2(__float2half(xv.z * mv.z), __float2half(xv.w * mv.w));
        }
#pragma unroll
        for (int i = 0; i < 16; ++i) {
            int idx = tid + i * 256;
            int kk = idx >> 5, r = idx & 31;
            *reinterpret_cast<__half*>(tsm + TP_XM_BYTES + r * TP_PITCH + kk * 2) =
                __float2half(A[(size_t)(kbase + kc + kk) * RNK + r]);
        }
        __syncthreads();
#pragma unroll
        for (int ks = 0; ks < 4; ++ks) {
            uint32_t a[4], b[2][4];
            ldmatrix_x4(a, a_addr + ks * 32);
            ldmatrix_x4(b[0], b_addr[0] + ks * 32);
            ldmatrix_x4(b[1], b_addr[1] + ks * 32);
#pragma unroll
            for (int j = 0; j < 4; ++j)
                mma_fp16(acc[j], a, b[j >> 1][(j & 1) * 2], b[j >> 1][(j & 1) * 2 + 1]);
        }
    }
    const int sl = slice * 2 + kh;
    const int g8 = lane >> 2;
    const int t4 = lane & 3;
#pragma unroll
    for (int j = 0; j < 4; ++j) {
        int r = j * 8 + t4 * 2;
        int m = m0 + mw + g8;
        *reinterpret_cast<float2*>(&g_tpart[sl][m][r]) = make_float2(acc[j][0], acc[j][1]);
        *reinterpret_cast<float2*>(&g_tpart[sl][m + 8][r]) = make_float2(acc[j][2], acc[j][3]);
    }
}

// ---------------- kernel #2: B pack (16 blocks) + t_pack (256 blocks) ----------
__global__ void __launch_bounds__(256) prep2_kernel(const float* __restrict__ Bm) {
    const int b = blockIdx.x;
    const int tid = threadIdx.x;
    if (b < 16) {
        int n = b * 256 + tid;
        __half* row = g_btcat + (size_t)n * 64;
#pragma unroll
        for (int r = 0; r < RNK; ++r) {
            __half h = __float2half(Bm[(size_t)r * N_ALL + n]);
            row[r] = h; row[32 + r] = h;
        }
    } else {
        int idx = (b - 16) * 256 + tid;
        int m = idx >> 3, rg = idx & 7, r = rg * 4;
        __half* row = g_tcat + (size_t)m * 64;
        float4 s = make_float4(0.f, 0.f, 0.f, 0.f);
#pragma unroll
        for (int sl = 0; sl < TP_SLICES; ++sl) {
            float4 p = *reinterpret_cast<const float4*>(&g_tpart[sl][m][r]);
            s.x += p.x; s.y += p.y; s.z += p.z; s.w += p.w;
        }
        float vals[4] = {s.x, s.y, s.z, s.w};
#pragma unroll
        for (int j = 0; j < 4; ++j) {
            __half h, l;
            split1h(vals[j], h, l);
            row[r + j] = h; row[32 + r + j] = l;
        }
    }
}

// ---------------- fused GEMM (R11 config + chunk rotation) ---------------------
// CTA tile 128x128, 256 threads (8 warps = 2M x 4N, warp tile 64x32), 2 CTAs/SM.
// 65 K-chunks of 64:  main chunks processed in bid-parity-rotated order
#define NCHUNK 65
#define PITCH_B 144
#define A_BYTES (128 * PITCH_B)
#define B_BYTES (128 * PITCH_B)
#define STAGE_BYTES (A_BYTES + B_BYTES)  // 36864
#define NSTAGE 3
#define GEMM_SMEM (NSTAGE * STAGE_BYTES) // 110592

__device__ __forceinline__ void load_chunk(int c, int stage, int tid, int m0, int n0,
                                           uint32_t smem_base) {
    const __half *pa, *pb;
    int lda, ldb, k0;
    if (c < 64) { pa = g_xhi;  pb = g_whi;   lda = K_ALL; ldb = K_ALL; k0 = c << 6; }
    else        { pa = g_tcat; pb = g_btcat; lda = 64;    ldb = 64;    k0 = 0; }
    uint32_t sA = smem_base + stage * STAGE_BYTES;
    uint32_t sB = sA + A_BYTES;
#pragma unroll
    for (int i = 0; i < 4; ++i) {
        int op = tid + i * 256;
        int row = op >> 3, col = op & 7;
        CP_ASYNC16(sA + (uint32_t)(row * PITCH_B + col * 16),
                   pa + (size_t)(m0 + row) * lda + k0 + col * 8);
        CP_ASYNC16(sB + (uint32_t)(row * PITCH_B + col * 16),
                   pb + (size_t)(n0 + row) * ldb + k0 + col * 8);
    }
}

// kernel #3: the GEMM
__global__ void __launch_bounds__(256, 2)
lora_gemm_kernel(float* __restrict__ out) {
    extern __shared__ __align__(1024) char smem[];
    const uint32_t smem_base = smem_u32(smem);
    const int tid = threadIdx.x;
    const int wid = tid >> 5;
    const int lane = tid & 31;
    // raster: groups of 16 m-tiles x 32 n-tiles
    const int gid = blockIdx.x >> 9;
    const int rr  = blockIdx.x & 511;
    const int m0 = (gid * 16 + (rr & 15)) * 128;
    const int n0 = (rr >> 4) * 128;
    const int m_w = (wid >> 2) * 64;
    const int n_w = (wid & 3) * 32;
    // chunk rotation: co-resident CTAs start at different K offsets
    const int crot = (blockIdx.x & 1) * 32;

    uint32_t aoff[4];
#pragma unroll
    for (int f = 0; f < 4; ++f)
        aoff[f] = (uint32_t)((m_w + f * 16 + (lane & 15)) * PITCH_B + (lane >> 4) * 16);
    uint32_t boff[2];
#pragma unroll
    for (int jj = 0; jj < 2; ++jj)
        boff[jj] = (uint32_t)(A_BYTES +
                              (n_w + jj * 16 + ((lane >> 4) << 3) + (lane & 7)) * PITCH_B +
                              ((lane >> 3) & 1) * 16);

    float acc[4][4][4];
#pragma unroll
    for (int f = 0; f < 4; ++f)
#pragma unroll
        for (int j = 0; j < 4; ++j)
#pragma unroll
            for (int v = 0; v < 4; ++v) acc[f][j][v] = 0.f;

    // chunk id mapping: iterations 0..63 cover main chunks (rotated), 64 = LoRA
    auto chunk_of = [&](int c) -> int {
        return (c < 64) ? ((c + crot) & 63) : 64;
    };

    load_chunk(chunk_of(0), 0, tid, m0, n0, smem_base);
    CP_ASYNC_COMMIT();
    load_chunk(chunk_of(1), 1, tid, m0, n0, smem_base);
    CP_ASYNC_COMMIT();

    int st_c = 0, st_l = 2;
    for (int c = 0; c < NCHUNK; ++c) {
        CP_ASYNC_WAIT(1);
        __syncthreads();
        const int cl = c + 2;
        const uint32_t sbase = smem_base + st_c * STAGE_BYTES;

        // per-ks interleave; next chunk's cp.async in the ks==1 shadow
#pragma unroll
        for (int ks = 0; ks < 4; ++ks) {
            uint32_t a[4][4], b[2][4];
#pragma unroll
            for (int jj = 0; jj < 2; ++jj) ldmatrix_x4(b[jj], sbase + boff[jj] + ks * 32);
#pragma unroll
            for (int f = 0; f < 4; ++f) ldmatrix_x4(a[f], sbase + aoff[f] + ks * 32);
            if (ks == 1 && cl < NCHUNK) load_chunk(chunk_of(cl), st_l, tid, m0, n0, smem_base);
#pragma unroll
            for (int f = 0; f < 4; ++f)
#pragma unroll
                for (int j = 0; j < 4; ++j)
                    mma_fp16(acc[f][j], a[f], b[j >> 1][(j & 1) * 2], b[j >> 1][(j & 1) * 2 + 1]);
        }
        CP_ASYNC_COMMIT();
        st_c = (st_c + 1 == NSTAGE) ? 0 : st_c + 1;
        st_l = (st_l + 1 == NSTAGE) ? 0 : st_l + 1;
    }

    // epilogue
    const int g8 = lane >> 2;
    const int t4 = lane & 3;
#pragma unroll
    for (int f = 0; f < 4; ++f) {
        const int mrow = m0 + m_w + f * 16 + g8;
#pragma unroll
        for (int j = 0; j < 4; ++j) {
            const int ncol = n0 + n_w + j * 8 + t4 * 2;
            float2 v0 = make_float2(acc[f][j][0], acc[f][j][1]);
            float2 v1 = make_float2(acc[f][j][2], acc[f][j][3]);
            *reinterpret_cast<float2*>(out + (size_t)mrow * N_ALL + ncol) = v0;
            *reinterpret_cast<float2*>(out + (size_t)(mrow + 8) * N_ALL + ncol) = v1;
        }
    }
}

// ---------------- launch ---------------------------------------------------------
extern "C" void kernel_launch(void* const* d_in, const int* in_sizes, int n_in,
                              void* d_out, int out_size) {
    const float* x    = (const float*)d_in[0];   // [8192, 4096]
    const float* W    = (const float*)d_in[1];   // [4096, 4096]
    const float* A    = (const float*)d_in[2];   // [4096, 32]
    const float* Bm   = (const float*)d_in[3];   // [32, 4096]
    const float* mask = (const float*)d_in[4];   // [8192, 4096]
    float* out = (float*)d_out;

    static bool attr_set = false;
    if (!attr_set) {
        cudaFuncSetAttribute(lora_gemm_kernel,
                             cudaFuncAttributeMaxDynamicSharedMemorySize, GEMM_SMEM);
        cudaFuncSetAttribute(prep1_kernel,
                             cudaFuncAttributeMaxDynamicSharedMemorySize, T_SMEM_BYTES);
        attr_set = true;
    }

    prep1_kernel<<<T_BLOCKS + W_BLOCKS, 256, T_SMEM_BYTES>>>(x, mask, A, (const float4*)W);
    prep2_kernel<<<272, 256>>>(Bm);
    lora_gemm_kernel<<<2048, 256, GEMM_SMEM>>>(out);
}

// round 16
// speedup vs baseline: 1.1158x; 1.0270x over previous
#include <cuda_runtime.h>
#include <cuda_fp16.h>
#include <cstdint>

// out[8192,4096] = x@W^T + ((x*mask)@A)@B   (fp32, SCALE=1)
// fp16 single-pass main GEMM; LoRA T via fp16 tensor-core GEMM (fp32 accum).
#define M_ALL 8192
#define N_ALL 4096
#define K_ALL 4096
#define RNK   32
#define TSLICES 8
#define TP_SLICES 16

// ---------------- scratch (__device__ globals; no allocs allowed) ------------
__device__ __align__(256) __half g_xhi[(size_t)M_ALL * K_ALL];
__device__ __align__(256) __half g_whi[(size_t)N_ALL * K_ALL];
__device__ __align__(256) __half g_tcat[(size_t)M_ALL * 64];    // [Th|Tl]
__device__ __align__(256) __half g_btcat[(size_t)N_ALL * 64];   // [Bh|Bh]
__device__ __align__(256) float g_tpart[TP_SLICES][M_ALL][RNK];

// ---------------- PTX helpers -------------------------------------------------
__device__ __forceinline__ uint32_t smem_u32(const void* p) {
    uint32_t a;
    asm("{ .reg .u64 t; cvta.to.shared.u64 t, %1; cvt.u32.u64 %0, t; }" : "=r"(a) : "l"(p));
    return a;
}
#define CP_ASYNC16(dst, src) \
    asm volatile("cp.async.cg.shared.global [%0], [%1], 16;" :: "r"((uint32_t)(dst)), "l"(src))
#define CP_ASYNC_COMMIT() asm volatile("cp.async.commit_group;" ::: "memory")
#define CP_ASYNC_WAIT(n)  asm volatile("cp.async.wait_group %0;" :: "n"(n) : "memory")

__device__ __forceinline__ void ldmatrix_x4(uint32_t* r, uint32_t addr) {
    asm volatile("ldmatrix.sync.aligned.m8n8.x4.shared.b16 {%0,%1,%2,%3}, [%4];"
                 : "=r"(r[0]), "=r"(r[1]), "=r"(r[2]), "=r"(r[3]) : "r"(addr));
}
__device__ __forceinline__ void mma_fp16(float* d, const uint32_t* a, uint32_t b0, uint32_t b1) {
    asm volatile(
        "mma.sync.aligned.m16n8k16.row.col.f32.f16.f16.f32 "
        "{%0,%1,%2,%3}, {%4,%5,%6,%7}, {%8,%9}, {%0,%1,%2,%3};"
        : "+f"(d[0]), "+f"(d[1]), "+f"(d[2]), "+f"(d[3])
        : "r"(a[0]), "r"(a[1]), "r"(a[2]), "r"(a[3]), "r"(b0), "r"(b1));
}
__device__ __forceinline__ void split1h(float v, __half& h, __half& l) {
    h = __float2half(v);
    l = __float2half(v - __half2float(h));
}

// ---------------- kernel #1: T partials (tensor core) + x->fp16 + W->fp16 ------
#define T_BLOCKS 1024
#define W_BLOCKS 4096
#define TP_PITCH 272
#define TP_XM_BYTES (64 * TP_PITCH)
#define TP_AT_BYTES (32 * TP_PITCH)
#define T_SMEM_BYTES (TP_XM_BYTES + TP_AT_BYTES)   // 26112

__global__ void __launch_bounds__(256, 4) prep1_kernel(const float* __restrict__ x,
                                                       const float* __restrict__ mask,
                                                       const float* __restrict__ A,
                                                       const float4* __restrict__ W) {
    extern __shared__ __align__(16) char tsm[];
    const int tid = threadIdx.x;
    const int bid = blockIdx.x;

    if (bid >= T_BLOCKS) {
        size_t base = (size_t)(bid - T_BLOCKS) * 1024 + tid;
        __half2* hi = reinterpret_cast<__half2*>(g_whi);
        float4 v[4];
#pragma unroll
        for (int u = 0; u < 4; ++u) v[u] = W[base + u * 256];
#pragma unroll
        for (int u = 0; u < 4; ++u) {
            size_t i = base + u * 256;
            hi[2 * i]     = __halves2half2(__float2half(v[u].x), __float2half(v[u].y));
            hi[2 * i + 1] = __halves2half2(__float2half(v[u].z), __float2half(v[u].w));
        }
        return;
    }

    const uint32_t smem_base = smem_u32(tsm);
    const uint32_t xm_base = smem_base;
    const uint32_t at_base = smem_base + TP_XM_BYTES;
    const int wid = tid >> 5;
    const int lane = tid & 31;
    const int slice = bid >> 7;            // 0..7
    const int m0 = (bid & 127) * 64;
    const int kbase = slice * (K_ALL / TSLICES);
    const int mw = (wid & 3) * 16;
    const int kh = wid >> 2;

    const uint32_t a_addr = xm_base + (uint32_t)(mw + (lane & 15)) * TP_PITCH +
                            (uint32_t)((lane >> 4) * 16 + kh * 128);
    uint32_t b_addr[2];
#pragma unroll
    for (int jj = 0; jj < 2; ++jj)
        b_addr[jj] = at_base +
                     (uint32_t)(jj * 16 + ((lane >> 4) << 3) + (lane & 7)) * TP_PITCH +
                     (uint32_t)(((lane >> 3) & 1) * 16 + kh * 128);

    float acc[4][4];
#pragma unroll
    for (int j = 0; j < 4; ++j)
#pragma unroll
        for (int v = 0; v < 4; ++v) acc[j][v] = 0.f;

    const float4* x4 = reinterpret_cast<const float4*>(x);
    const float4* m4 = reinterpret_cast<const float4*>(mask);
    __half2* xh2 = reinterpret_cast<__half2*>(g_xhi);

    for (int kc = 0; kc < K_ALL / TSLICES; kc += 128) {
        __syncthreads();
#pragma unroll
        for (int i = 0; i < 8; ++i) {
            int idx = tid + i * 256;
            int row = idx >> 5, c4 = idx & 31;
            size_t g = ((size_t)(m0 + row) * K_ALL + kbase + kc) / 4 + c4;
            float4 xv = x4[g];
            float4 mv = m4[g];
            xh2[2 * g]     = __halves2half2(__float2half(xv.x), __float2half(xv.y));
            xh2[2 * g + 1] = __halves2half2(__float2half(xv.z), __float2half(xv.w));
            __half2* dst = reinterpret_cast<__half2*>(tsm + row * TP_PITCH + c4 * 8);
            dst[0] = __halves2half2(__float2half(xv.x * mv.x), __float2half(xv.y * mv.y));
            dst[1] = __halves2half2(__float2half(xv.z * mv.z), __float2half(xv.w * mv.w));
        }
#pragma unroll
        for (int i = 0; i < 16; ++i) {
            int idx = tid + i * 256;
            int kk = idx >> 5, r = idx & 31;
            *reinterpret_cast<__half*>(tsm + TP_XM_BYTES + r * TP_PITCH + kk * 2) =
                __float2half(A[(size_t)(kbase + kc + kk) * RNK + r]);
        }
        __syncthreads();
#pragma unroll
        for (int ks = 0; ks < 4; ++ks) {
            uint32_t a[4], b[2][4];
            ldmatrix_x4(a, a_addr + ks * 32);
            ldmatrix_x4(b[0], b_addr[0] + ks * 32);
            ldmatrix_x4(b[1], b_addr[1] + ks * 32);
#pragma unroll
            for (int j = 0; j < 4; ++j)
                mma_fp16(acc[j], a, b[j >> 1][(j & 1) * 2], b[j >> 1][(j & 1) * 2 + 1]);
        }
    }
    const int sl = slice * 2 + kh;
    const int g8 = lane >> 2;
    const int t4 = lane & 3;
#pragma unroll
    for (int j = 0; j < 4; ++j) {
        int r = j * 8 + t4 * 2;
        int m = m0 + mw + g8;
        *reinterpret_cast<float2*>(&g_tpart[sl][m][r]) = make_float2(acc[j][0], acc[j][1]);
        *reinterpret_cast<float2*>(&g_tpart[sl][m + 8][r]) = make_float2(acc[j][2], acc[j][3]);
    }
}

// ---------------- kernel #2: B pack (16 blocks) + t_pack (256 blocks) ----------
__global__ void __launch_bounds__(256) prep2_kernel(const float* __restrict__ Bm) {
    const int b = blockIdx.x;
    const int tid = threadIdx.x;
    if (b < 16) {
        int n = b * 256 + tid;
        __half* row = g_btcat + (size_t)n * 64;
#pragma unroll
        for (int r = 0; r < RNK; ++r) {
            __half h = __float2half(Bm[(size_t)r * N_ALL + n]);
            row[r] = h; row[32 + r] = h;
        }
    } else {
        int idx = (b - 16) * 256 + tid;
        int m = idx >> 3, rg = idx & 7, r = rg * 4;
        __half* row = g_tcat + (size_t)m * 64;
        float4 s = make_float4(0.f, 0.f, 0.f, 0.f);
#pragma unroll
        for (int sl = 0; sl < TP_SLICES; ++sl) {
            float4 p = *reinterpret_cast<const float4*>(&g_tpart[sl][m][r]);
            s.x += p.x; s.y += p.y; s.z += p.z; s.w += p.w;
        }
        float vals[4] = {s.x, s.y, s.z, s.w};
#pragma unroll
        for (int j = 0; j < 4; ++j) {
            __half h, l;
            split1h(vals[j], h, l);
            row[r + j] = h; row[32 + r + j] = l;
        }
    }
}

// ---------------- fused GEMM (R14 config, finer chunk rotation) ----------------
// CTA tile 128x128, 256 threads (8 warps = 2M x 4N, warp tile 64x32), 2 CTAs/SM.
// 65 K-chunks of 64:  main chunks processed in bid-rotated order (4 phases)
#define NCHUNK 65
#define PITCH_B 144
#define A_BYTES (128 * PITCH_B)
#define B_BYTES (128 * PITCH_B)
#define STAGE_BYTES (A_BYTES + B_BYTES)  // 36864
#define NSTAGE 3
#define GEMM_SMEM (NSTAGE * STAGE_BYTES) // 110592

__device__ __forceinline__ void load_chunk(int c, int stage, int tid, int m0, int n0,
                                           uint32_t smem_base) {
    const __half *pa, *pb;
    int lda, ldb, k0;
    if (c < 64) { pa = g_xhi;  pb = g_whi;   lda = K_ALL; ldb = K_ALL; k0 = c << 6; }
    else        { pa = g_tcat; pb = g_btcat; lda = 64;    ldb = 64;    k0 = 0; }
    uint32_t sA = smem_base + stage * STAGE_BYTES;
    uint32_t sB = sA + A_BYTES;
#pragma unroll
    for (int i = 0; i < 4; ++i) {
        int op = tid + i * 256;
        int row = op >> 3, col = op & 7;
        CP_ASYNC16(sA + (uint32_t)(row * PITCH_B + col * 16),
                   pa + (size_t)(m0 + row) * lda + k0 + col * 8);
        CP_ASYNC16(sB + (uint32_t)(row * PITCH_B + col * 16),
                   pb + (size_t)(n0 + row) * ldb + k0 + col * 8);
    }
}

// kernel #3: the GEMM
__global__ void __launch_bounds__(256, 2)
lora_gemm_kernel(float* __restrict__ out) {
    extern __shared__ __align__(1024) char smem[];
    const uint32_t smem_base = smem_u32(smem);
    const int tid = threadIdx.x;
    const int wid = tid >> 5;
    const int lane = tid & 31;
    // raster: groups of 16 m-tiles x 32 n-tiles
    const int gid = blockIdx.x >> 9;
    const int rr  = blockIdx.x & 511;
    const int m0 = (gid * 16 + (rr & 15)) * 128;
    const int n0 = (rr >> 4) * 128;
    const int m_w = (wid >> 2) * 64;
    const int n_w = (wid & 3) * 32;
    // chunk rotation: 4 phases across nearby CTAs
    const int crot = (blockIdx.x & 3) * 16;

    uint32_t aoff[4];
#pragma unroll
    for (int f = 0; f < 4; ++f)
        aoff[f] = (uint32_t)((m_w + f * 16 + (lane & 15)) * PITCH_B + (lane >> 4) * 16);
    uint32_t boff[2];
#pragma unroll
    for (int jj = 0; jj < 2; ++jj)
        boff[jj] = (uint32_t)(A_BYTES +
                              (n_w + jj * 16 + ((lane >> 4) << 3) + (lane & 7)) * PITCH_B +
                              ((lane >> 3) & 1) * 16);

    float acc[4][4][4];
#pragma unroll
    for (int f = 0; f < 4; ++f)
#pragma unroll
        for (int j = 0; j < 4; ++j)
#pragma unroll
            for (int v = 0; v < 4; ++v) acc[f][j][v] = 0.f;

    // chunk id mapping: iterations 0..63 cover main chunks (rotated), 64 = LoRA
    auto chunk_of = [&](int c) -> int {
        return (c < 64) ? ((c + crot) & 63) : 64;
    };

    load_chunk(chunk_of(0), 0, tid, m0, n0, smem_base);
    CP_ASYNC_COMMIT();
    load_chunk(chunk_of(1), 1, tid, m0, n0, smem_base);
    CP_ASYNC_COMMIT();

    int st_c = 0, st_l = 2;
    for (int c = 0; c < NCHUNK; ++c) {
        CP_ASYNC_WAIT(1);
        __syncthreads();
        const int cl = c + 2;
        const uint32_t sbase = smem_base + st_c * STAGE_BYTES;

        // per-ks interleave; next chunk's cp.async in the ks==1 shadow
#pragma unroll
        for (int ks = 0; ks < 4; ++ks) {
            uint32_t a[4][4], b[2][4];
#pragma unroll
            for (int jj = 0; jj < 2; ++jj) ldmatrix_x4(b[jj], sbase + boff[jj] + ks * 32);
#pragma unroll
            for (int f = 0; f < 4; ++f) ldmatrix_x4(a[f], sbase + aoff[f] + ks * 32);
            if (ks == 1 && cl < NCHUNK) load_chunk(chunk_of(cl), st_l, tid, m0, n0, smem_base);
#pragma unroll
            for (int f = 0; f < 4; ++f)
#pragma unroll
                for (int j = 0; j < 4; ++j)
                    mma_fp16(acc[f][j], a[f], b[j >> 1][(j & 1) * 2], b[j >> 1][(j & 1) * 2 + 1]);
        }
        CP_ASYNC_COMMIT();
        st_c = (st_c + 1 == NSTAGE) ? 0 : st_c + 1;
        st_l = (st_l + 1 == NSTAGE) ? 0 : st_l + 1;
    }

    // epilogue
    const int g8 = lane >> 2;
    const int t4 = lane & 3;
#pragma unroll
    for (int f = 0; f < 4; ++f) {
        const int mrow = m0 + m_w + f * 16 + g8;
#pragma unroll
        for (int j = 0; j < 4; ++j) {
            const int ncol = n0 + n_w + j * 8 + t4 * 2;
            float2 v0 = make_float2(acc[f][j][0], acc[f][j][1]);
            float2 v1 = make_float2(acc[f][j][2], acc[f][j][3]);
            *reinterpret_cast<float2*>(out + (size_t)mrow * N_ALL + ncol) = v0;
            *reinterpret_cast<float2*>(out + (size_t)(mrow + 8) * N_ALL + ncol) = v1;
        }
    }
}

// ---------------- launch ---------------------------------------------------------
extern "C" void kernel_launch(void* const* d_in, const int* in_sizes, int n_in,
                              void* d_out, int out_size) {
    const float* x    = (const float*)d_in[0];   // [8192, 4096]
    const float* W    = (const float*)d_in[1];   // [4096, 4096]
    const float* A    = (const float*)d_in[2];   // [4096, 32]
    const float* Bm   = (const float*)d_in[3];   // [32, 4096]
    const float* mask = (const float*)d_in[4];   // [8192, 4096]
    float* out = (float*)d_out;

    static bool attr_set = false;
    if (!attr_set) {
        cudaFuncSetAttribute(lora_gemm_kernel,
                             cudaFuncAttributeMaxDynamicSharedMemorySize, GEMM_SMEM);
        cudaFuncSetAttribute(prep1_kernel,
                             cudaFuncAttributeMaxDynamicSharedMemorySize, T_SMEM_BYTES);
        attr_set = true;
    }

    prep1_kernel<<<T_BLOCKS + W_BLOCKS, 256, T_SMEM_BYTES>>>(x, mask, A, (const float4*)W);
    prep2_kernel<<<272, 256>>>(Bm);
    lora_gemm_kernel<<<2048, 256, GEMM_SMEM>>>(out);
}